// round 15
// baseline (speedup 1.0000x reference)
#include <cuda_runtime.h>
#include <cstdint>

#define BATCH 8
#define NA 3
#define NC 80
#define HH 160
#define WW 160
#define HW 25600      // HH*WW
#define NPB 76800     // NA*HW candidates per batch
#define BPB 75        // blocks per batch (1024 elements each)
#define TOPKK 100
#define NBIN 4096
#define CANDCAP 192
#define LNEED 6       // local per-block eval target: 75*6 = 450 >= 100 guaranteed

typedef unsigned long long u64;
typedef unsigned int u32;
typedef unsigned char u8;

// ---------------- static device scratch (zero-init at load; finalize winner re-zeros) -----------
__device__ u64  g_keys[BATCH * NPB];       // evaluated score keys per batch (E1 then E2)
__device__ int  g_eidx[BATCH * NPB];       // E2 work queue (indices)
__device__ u8   g_cls[BATCH * NPB];        // argmax class per evaluated candidate
__device__ u32  g_schist[BATCH * NBIN];    // histogram of evaluated score bits (key >> 35)
__device__ int  g_cnt1[BATCH], g_cnt2[BATCH], g_fetch[BATCH];
__device__ float g_S2[BATCH];              // s-domain lower bound implied by 100th score
__device__ int  g_tick2[BATCH], g_tick3[BATCH], g_tick4[BATCH];
__device__ int  g_flag2[BATCH], g_flag3[BATCH];
__device__ int  g_e2tot[BATCH];

__device__ __forceinline__ float fsig(float x) { return 1.0f / (1.0f + __expf(-x)); }

// total-order mapping for float bits (handles negatives)
__device__ __forceinline__ u32 ford(float f) {
    u32 b = __float_as_uint(f);
    return b ^ ((b >> 31) ? 0xFFFFFFFFu : 0x80000000u);
}

// warp-collective: max+argmax over 80 class logits -> exact score key; writes class byte
__device__ __forceinline__ u64 evalCand(const float* __restrict__ cls,
                                        const float* __restrict__ obj,
                                        const float* __restrict__ qual,
                                        int b, int idx, int lane) {
    int a = idx / HW;
    int pix = idx - a * HW;
    const float* cp = cls + (size_t)(b * NA + a) * NC * HW + pix;
    float m = cp[(size_t)lane * HW];
    int c = lane;
    float v = cp[(size_t)(lane + 32) * HW];
    if (v > m) { m = v; c = lane + 32; }
    if (lane < 16) {
        float w = cp[(size_t)(lane + 64) * HW];
        if (w > m) { m = w; c = lane + 64; }
    }
#pragma unroll
    for (int off = 16; off; off >>= 1) {
        float om = __shfl_xor_sync(0xffffffffu, m, off);
        int   oc = __shfl_xor_sync(0xffffffffu, c, off);
        if (om > m || (om == m && oc < c)) { m = om; c = oc; }
    }
    if (lane == 0) g_cls[b * NPB + idx] = (u8)c;
    float o = obj[b * NPB + idx];                // broadcast load
    float q = qual[b * NPB + idx];
    float score = __fdiv_rn(1.0f,
        (1.0f + __expf(-o)) * (1.0f + __expf(-q)) * (1.0f + __expf(-m)));
    return ((u64)__float_as_uint(score) << 17) | (u32)(NPB - 1 - idx);
}

// 256-thread top-K boundary pick over smem hist h (bpt bins/thread).
__device__ __forceinline__ void pickTop(u32* h, int bpt, u32* scan, int need,
                                        int* sd, int* sLab, int* sC) {
    int t = threadIdx.x;
    int base = t * bpt;
    u32 ssum = 0;
    for (int q = 0; q < bpt; q++) ssum += h[base + q];
    scan[t] = ssum;
    __syncthreads();
    for (int d = 1; d < 256; d <<= 1) {          // inclusive suffix scan
        u32 v = (t + d < 256) ? scan[t + d] : 0u;
        __syncthreads();
        scan[t] += v;
        __syncthreads();
    }
    u32 above = (t < 255) ? scan[t + 1] : 0u;
    if ((int)scan[t] >= need && (int)above < need) {   // exactly one thread
        u32 cum = above;
        int d;
        for (d = base + bpt - 1;; d--) {
            if ((int)(cum + h[d]) >= need) break;
            cum += h[d];
        }
        *sd = d; *sLab = (int)cum; *sC = (int)(cum + h[d]);
    }
    __syncthreads();
}

// =================== single fused kernel: 600 blocks, all co-resident ===================
__global__ void __launch_bounds__(256, 5) fusedK(const float* __restrict__ cls,
                                                 const float* __restrict__ obj,
                                                 const float* __restrict__ qual,
                                                 const float* __restrict__ box,
                                                 const float* __restrict__ anch,
                                                 float* __restrict__ out) {
    __shared__ u32 shh[NBIN];        // 16 KB: local hist / T2 hist / finalize level-0 hist
    __shared__ u32 scan[256];        // 1 KB
    __shared__ int sbuf[1024];       // 4 KB: candidate buffer / finalize sub-hist
    __shared__ u64 cand[CANDCAP];    // 1.5 KB
    __shared__ int s_n, s_pos, s_last, s_d, s_L, s_C, s_cnt;

    int tid = threadIdx.x, lane = tid & 31, warp = tid >> 5;
    int bid = blockIdx.x;
    int b = bid / BPB;
    int tile0 = (bid - b * BPB) * 1024;          // batch-relative start

    // ---- load once; s lives in registers for the whole kernel ----
    int g0 = b * NPB + tile0 + tid * 4;
    float4 o4 = *reinterpret_cast<const float4*>(obj + g0);
    float4 q4 = *reinterpret_cast<const float4*>(qual + g0);
    float ss[4] = {o4.x + q4.x, o4.y + q4.y, o4.z + q4.z, o4.w + q4.w};

    // ---- local 4096-bin hist of this block's 1024 s values ----
    for (int j = tid; j < NBIN; j += 256) shh[j] = 0;
    __syncthreads();
#pragma unroll
    for (int j = 0; j < 4; j++) atomicAdd(&shh[ford(ss[j]) >> 20], 1u);
    __syncthreads();
    pickTop(shh, 16, scan, LNEED, &s_d, &s_L, &s_C);
    u32 T1 = (u32)s_d;                           // block-local threshold (>=LNEED members)

    // ---- E1: collect + eval everything with local bin >= T1 ----
    if (tid == 0) s_n = 0;
    __syncthreads();
#pragma unroll
    for (int j = 0; j < 4; j++) {
        if ((ford(ss[j]) >> 20) >= T1) {
            int p = atomicAdd(&s_n, 1);          // shared atomic
            sbuf[p] = tile0 + tid * 4 + j;
        }
    }
    __syncthreads();
    if (tid == 0) s_pos = s_n ? atomicAdd(&g_cnt1[b], s_n) : 0;
    __syncthreads();
    int n = s_n, pos = s_pos;
    for (int j = warp; j < n; j += 8) {
        u64 key = evalCand(cls, obj, qual, b, sbuf[j], lane);
        if (lane == 0) {
            g_keys[(size_t)b * NPB + pos + j] = key;
            atomicAdd(&g_schist[b * NBIN + (u32)(key >> 35)], 1u);
        }
    }
    __threadfence();                             // every thread releases its own writes
    __syncthreads();

    // ---- ticket: 75th block of batch computes T2 -> S2, raises flag2 ----
    if (tid == 0) s_last = (atomicAdd(&g_tick2[b], 1) == BPB - 1) ? 1 : 0;
    __syncthreads();
    if (s_last) {
        const u32* gh = g_schist + b * NBIN;
        for (int j = tid; j < NBIN; j += 256) shh[j] = gh[j];
        __syncthreads();
        pickTop(shh, 16, scan, TOPKK, &s_d, &s_L, &s_C);
        if (tid == 0) {
            float v2 = __uint_as_float(((u32)s_d) << 18);   // lower edge of boundary bin
            float S2;
            float sq = sqrtf(v2);
            if (sq < 1e-4f) S2 = -3.0e38f;       // degenerate: evaluate everything (exact)
            else {
                if (sq > 0.999f) sq = 0.999f;    // clamp DOWN -> safe (larger E2)
                S2 = 2.0f * (__logf(sq) - __logf(1.0f - sq)) - 0.02f;  // slack >> rounding
            }
            g_S2[b] = S2;
            __threadfence();
            *(volatile int*)&g_flag2[b] = 1;
        }
    }

    // ---- wait for S2 (deadlock-free: all 600 blocks co-resident at occ 5) ----
    if (tid == 0) {
        volatile int* vf = &g_flag2[b];
        while (*vf == 0) __nanosleep(64);
    }
    __syncthreads();
    __threadfence();                             // acquire
    float S2 = g_S2[b];
    int c1 = g_cnt1[b];                          // final: all E1 done before flag2

    // ---- E2a: push candidate indices to the per-batch queue (no eval yet) ----
    if (tid == 0) s_n = 0;
    __syncthreads();
#pragma unroll
    for (int j = 0; j < 4; j++) {
        if (ss[j] >= S2 && (ford(ss[j]) >> 20) < T1) {
            int p = atomicAdd(&s_n, 1);
            sbuf[p] = tile0 + tid * 4 + j;
        }
    }
    __syncthreads();
    if (tid == 0) s_pos = s_n ? atomicAdd(&g_cnt2[b], s_n) : 0;
    __syncthreads();
    n = s_n; pos = s_pos;
    for (int j = tid; j < n; j += 256)
        g_eidx[b * NPB + pos + j] = sbuf[j];     // coalesced queue append
    __threadfence();
    __syncthreads();

    // ---- ticket4: last block latches queue length, raises flag3 ----
    if (tid == 0) {
        if (atomicAdd(&g_tick4[b], 1) == BPB - 1) {
            g_e2tot[b] = g_cnt2[b];
            __threadfence();
            *(volatile int*)&g_flag3[b] = 1;
        }
    }
    if (tid == 0) {
        volatile int* vf = &g_flag3[b];
        while (*vf == 0) __nanosleep(64);
    }
    __syncthreads();
    __threadfence();                             // acquire queue contents
    int tot = g_e2tot[b];

    // ---- E2b: work-steal evaluation (balanced across all 75 blocks) ----
    for (;;) {
        if (tid == 0) s_pos = atomicAdd(&g_fetch[b], 8);
        __syncthreads();
        int base = s_pos;
        if (base >= tot) break;
        int j = base + warp;
        if (j < tot) {
            u64 key = evalCand(cls, obj, qual, b, g_eidx[b * NPB + j], lane);
            if (lane == 0) g_keys[(size_t)b * NPB + c1 + j] = key;
        }
        __syncthreads();
    }
    __threadfence();
    __syncthreads();

    // ---- ticket3: last block of batch finalizes (no spin, no extra blocks) ----
    if (tid == 0) s_last = (atomicAdd(&g_tick3[b], 1) == BPB - 1) ? 1 : 0;
    __syncthreads();
    if (!s_last) return;

    // ======== finalize batch b: exact top-100 over all M evaluated keys ========
    int M = c1 + tot;
    const u64* keys = g_keys + (size_t)b * NPB;

    for (int j = tid; j < NBIN; j += 256) shh[j] = 0;
    __syncthreads();
    for (int j = tid; j < M; j += 256)
        atomicAdd(&shh[(u32)(keys[j] >> 35)], 1u);
    __syncthreads();
    pickTop(shh, 16, scan, TOPKK, &s_d, &s_L, &s_C);
    u64 P = (u64)(u32)s_d;
    int s = 35, L = s_L, C = s_C;
    __syncthreads();

    // 10-bit refinement (25, 15, 5); L < 100 invariant; at s=5 bucket <= 32 -> C <= 131.
    u32* subh = reinterpret_cast<u32*>(sbuf);
    while (C > CANDCAP && s > 5) {
        int s2 = s - 10;
        for (int j = tid; j < 1024; j += 256) subh[j] = 0;
        __syncthreads();
        for (int j = tid; j < M; j += 256) {
            u64 k = keys[j];
            if ((k >> s) == P) atomicAdd(&subh[(u32)(k >> s2) & 1023], 1u);
        }
        __syncthreads();
        pickTop(subh, 4, scan, TOPKK - L, &s_d, &s_L, &s_C);
        int Lsub = s_L, Csub = s_C;
        __syncthreads();
        P = (P << 10) | (u32)s_d;
        s = s2;
        C = L + Csub;
        L = L + Lsub;
    }

    if (tid == 0) s_cnt = 0;
    __syncthreads();
    for (int j = tid; j < M; j += 256) {
        u64 k = keys[j];
        if ((k >> s) >= P) {
            int p = atomicAdd(&s_cnt, 1);
            if (p < CANDCAP) cand[p] = k;
        }
    }
    __syncthreads();
    int Cn = min(s_cnt, CANDCAP);

    // rank by counting (keys distinct -> exact permutation), decode inline
    for (int i = tid; i < Cn; i += 256) {
        u64 k = cand[i];
        int r = 0;
        for (int j = 0; j < Cn; j++) r += (cand[j] > k);
        if (r < TOPKK) {
            u32 sb = (u32)(k >> 17);
            int idx = NPB - 1 - (int)(k & 0x1FFFFu);
            int a = idx / HW;
            int pix = idx - a * HW;
            int y = pix / WW;
            int x = pix - y * WW;
            int c = (int)g_cls[b * NPB + idx];
            const float* bp = box + (size_t)(b * NA + a) * 4 * HW + pix;
            float tx = bp[0];
            float ty = bp[(size_t)HW];
            float tw = bp[2 * (size_t)HW];
            float th = bp[3 * (size_t)HW];
            float aw = anch[a * 2 + 0];
            float ah = anch[a * 2 + 1];
            float cx = (fsig(tx) + (float)x) / (float)WW;
            float cy = (fsig(ty) + (float)y) / (float)HH;
            // faithful softplus: relu(x) + log1p(exp(-|x|))
            float spw = fmaxf(tw, 0.0f) + log1pf(__expf(-fabsf(tw)));
            float sph = fmaxf(th, 0.0f) + log1pf(__expf(-fabsf(th)));
            float* o = out + ((size_t)b * TOPKK + r) * 6;
            o[0] = __uint_as_float(sb);
            o[1] = (float)c;
            o[2] = cx;
            o[3] = cy;
            o[4] = aw * spw;
            o[5] = ah * sph;
        }
    }

    // reset batch-b scratch for the next replay (device globals start zeroed on load)
    __syncthreads();
    for (int j = tid; j < NBIN; j += 256) g_schist[b * NBIN + j] = 0;
    if (tid == 0) {
        g_cnt1[b] = 0; g_cnt2[b] = 0; g_fetch[b] = 0; g_e2tot[b] = 0;
        g_tick2[b] = 0; g_tick3[b] = 0; g_tick4[b] = 0;
        g_flag2[b] = 0; g_flag3[b] = 0;
    }
}

// ---------------- launch ----------------
extern "C" void kernel_launch(void* const* d_in, const int* in_sizes, int n_in,
                              void* d_out, int out_size) {
    const float* box  = (const float*)d_in[0];
    const float* obj  = (const float*)d_in[1];
    const float* qual = (const float*)d_in[2];
    const float* cls  = (const float*)d_in[3];
    const float* anch = (const float*)d_in[4];
    int seen = 0;
    for (int i = 0; i < n_in; i++) {
        int s = in_sizes[i];
        if (s == BATCH * NA * 4 * HW) box = (const float*)d_in[i];
        else if (s == BATCH * NA * NC * HW) cls = (const float*)d_in[i];
        else if (s == NA * 2) anch = (const float*)d_in[i];
        else if (s == BATCH * NA * HW) {
            if (seen == 0) obj = (const float*)d_in[i];
            else qual = (const float*)d_in[i];
            seen++;
        }
    }
    float* out = (float*)d_out;

    fusedK<<<BATCH * BPB, 256>>>(cls, obj, qual, box, anch, out);
}

// round 16
// speedup vs baseline: 1.1395x; 1.1395x over previous
#include <cuda_runtime.h>
#include <cstdint>

#define BATCH 8
#define NA 3
#define NC 80
#define HH 160
#define WW 160
#define HW 25600      // HH*WW
#define NPB 76800     // NA*HW candidates per batch
#define BPB 75        // blocks per batch (1024 elements each)
#define TOPKK 100
#define NBIN 4096
#define CANDCAP 192
#define LNEED 6       // local per-block eval target: 75*6 = 450 >= 100 guaranteed

typedef unsigned long long u64;
typedef unsigned int u32;
typedef unsigned char u8;

// ---------------- static device scratch (zero-init at load; finalize winner re-zeros) -----------
__device__ u64  g_keys[BATCH * NPB];       // evaluated score keys per batch (E1 then E2)
__device__ u8   g_cls[BATCH * NPB];        // argmax class per evaluated candidate
__device__ u32  g_schist[BATCH * NBIN];    // histogram of evaluated score bits (key >> 35)
__device__ int  g_cnt1[BATCH], g_cnt2[BATCH];
__device__ float g_S2[BATCH];              // s-domain lower bound implied by 100th score
__device__ int  g_tick2[BATCH], g_tick3[BATCH], g_flag2[BATCH];

__device__ __forceinline__ float fsig(float x) { return 1.0f / (1.0f + __expf(-x)); }

// total-order mapping for float bits (handles negatives)
__device__ __forceinline__ u32 ford(float f) {
    u32 b = __float_as_uint(f);
    return b ^ ((b >> 31) ? 0xFFFFFFFFu : 0x80000000u);
}

// warp-collective: max+argmax over 80 class logits -> exact score key; writes class byte
__device__ __forceinline__ u64 evalCand(const float* __restrict__ cls,
                                        const float* __restrict__ obj,
                                        const float* __restrict__ qual,
                                        int b, int idx, int lane) {
    int a = idx / HW;
    int pix = idx - a * HW;
    const float* cp = cls + (size_t)(b * NA + a) * NC * HW + pix;
    float m = cp[(size_t)lane * HW];
    int c = lane;
    float v = cp[(size_t)(lane + 32) * HW];
    if (v > m) { m = v; c = lane + 32; }
    if (lane < 16) {
        float w = cp[(size_t)(lane + 64) * HW];
        if (w > m) { m = w; c = lane + 64; }
    }
#pragma unroll
    for (int off = 16; off; off >>= 1) {
        float om = __shfl_xor_sync(0xffffffffu, m, off);
        int   oc = __shfl_xor_sync(0xffffffffu, c, off);
        if (om > m || (om == m && oc < c)) { m = om; c = oc; }
    }
    if (lane == 0) g_cls[b * NPB + idx] = (u8)c;
    float o = obj[b * NPB + idx];                // broadcast load
    float q = qual[b * NPB + idx];
    float score = __fdiv_rn(1.0f,
        (1.0f + __expf(-o)) * (1.0f + __expf(-q)) * (1.0f + __expf(-m)));
    return ((u64)__float_as_uint(score) << 17) | (u32)(NPB - 1 - idx);
}

// 256-thread top-K boundary pick over smem hist h (bpt bins/thread) — shuffle-scan version.
// Outputs via shared ints: *sd = boundary bin, *sLab = strictly-above count, *sC = count >= bin.
// Exactly 2 __syncthreads.
__device__ __forceinline__ void pickTop(u32* h, int bpt, u32* wsum, int need,
                                        int* sd, int* sLab, int* sC) {
    int t = threadIdx.x, lane = t & 31, w = t >> 5;
    int base = t * bpt;
    u32 ssum = 0;
    for (int q = 0; q < bpt; q++) ssum += h[base + q];
    // intra-warp inclusive suffix scan (Kogge-Stone via shfl_down)
    u32 val = ssum;
#pragma unroll
    for (int off = 1; off < 32; off <<= 1) {
        u32 v = __shfl_down_sync(0xffffffffu, val, off);
        if (lane + off < 32) val += v;
    }
    if (lane == 0) wsum[w] = val;                // warp totals
    __syncthreads();
    u32 after = 0;
    for (int j = w + 1; j < 8; j++) after += wsum[j];
    u32 scan = val + after;                      // inclusive suffix over all 256
    u32 above = scan - ssum;                     // suffix starting at t+1
    if ((int)scan >= need && (int)above < need) {     // exactly one thread
        u32 cum = above;
        int d;
        for (d = base + bpt - 1;; d--) {
            if ((int)(cum + h[d]) >= need) break;
            cum += h[d];
        }
        *sd = d; *sLab = (int)cum; *sC = (int)(cum + h[d]);
    }
    __syncthreads();
}

// =================== single fused kernel: 600 blocks, all co-resident ===================
__global__ void __launch_bounds__(256, 5) fusedK(const float* __restrict__ cls,
                                                 const float* __restrict__ obj,
                                                 const float* __restrict__ qual,
                                                 const float* __restrict__ box,
                                                 const float* __restrict__ anch,
                                                 float* __restrict__ out) {
    __shared__ u32 shh[NBIN];        // 16 KB: local hist / T2 hist / finalize level-0 hist
    __shared__ u32 wsum[8];          // pickTop warp totals
    __shared__ int sbuf[1024];       // 4 KB: candidate buffer / finalize sub-hist
    __shared__ u64 cand[CANDCAP];    // 1.5 KB
    __shared__ int s_n, s_pos, s_last, s_d, s_L, s_C, s_cnt;

    int tid = threadIdx.x, lane = tid & 31, warp = tid >> 5;
    int bid = blockIdx.x;
    int b = bid / BPB;
    int tile0 = (bid - b * BPB) * 1024;          // batch-relative start

    // ---- load once; s lives in registers for the whole kernel ----
    int g0 = b * NPB + tile0 + tid * 4;
    float4 o4 = *reinterpret_cast<const float4*>(obj + g0);
    float4 q4 = *reinterpret_cast<const float4*>(qual + g0);
    float ss[4] = {o4.x + q4.x, o4.y + q4.y, o4.z + q4.z, o4.w + q4.w};

    // ---- local 4096-bin hist of this block's 1024 s values (vectorized zero) ----
    {
        uint4* z = reinterpret_cast<uint4*>(shh);
        uint4 zero4 = make_uint4(0, 0, 0, 0);
#pragma unroll
        for (int j = 0; j < 4; j++) z[tid + j * 256] = zero4;
    }
    __syncthreads();
#pragma unroll
    for (int j = 0; j < 4; j++) atomicAdd(&shh[ford(ss[j]) >> 20], 1u);
    __syncthreads();
    pickTop(shh, 16, wsum, LNEED, &s_d, &s_L, &s_C);
    u32 T1 = (u32)s_d;                           // block-local threshold (>=LNEED members)

    // ---- E1: collect + eval everything with local bin >= T1 ----
    if (tid == 0) s_n = 0;
    __syncthreads();
#pragma unroll
    for (int j = 0; j < 4; j++) {
        if ((ford(ss[j]) >> 20) >= T1) {
            int p = atomicAdd(&s_n, 1);          // shared atomic
            sbuf[p] = tile0 + tid * 4 + j;
        }
    }
    __syncthreads();
    if (tid == 0) s_pos = s_n ? atomicAdd(&g_cnt1[b], s_n) : 0;
    __syncthreads();
    int n = s_n, pos = s_pos;
    for (int j = warp; j < n; j += 8) {
        u64 key = evalCand(cls, obj, qual, b, sbuf[j], lane);
        if (lane == 0) {
            g_keys[(size_t)b * NPB + pos + j] = key;
            atomicAdd(&g_schist[b * NBIN + (u32)(key >> 35)], 1u);
        }
    }
    if (lane == 0) __threadfence();              // only lane0 threads wrote globals
    __syncthreads();

    // ---- ticket: 75th block of batch computes T2 -> S2, raises flag2 ----
    if (tid == 0) s_last = (atomicAdd(&g_tick2[b], 1) == BPB - 1) ? 1 : 0;
    __syncthreads();
    if (s_last) {
        const u32* gh = g_schist + b * NBIN;
        for (int j = tid; j < NBIN; j += 256) shh[j] = gh[j];
        __syncthreads();
        pickTop(shh, 16, wsum, TOPKK, &s_d, &s_L, &s_C);
        if (tid == 0) {
            float v2 = __uint_as_float(((u32)s_d) << 18);   // lower edge of boundary bin
            float S2;
            float sq = sqrtf(v2);
            if (sq < 1e-4f) S2 = -3.0e38f;       // degenerate: evaluate everything (exact)
            else {
                if (sq > 0.999f) sq = 0.999f;    // clamp DOWN -> safe (larger E2)
                S2 = 2.0f * (__logf(sq) - __logf(1.0f - sq)) - 0.02f;  // slack >> rounding
            }
            g_S2[b] = S2;
            __threadfence();
            *(volatile int*)&g_flag2[b] = 1;
        }
    }

    // ---- wait for S2 (deadlock-free: all 600 blocks co-resident at occ 5) ----
    if (tid == 0) {
        volatile int* vf = &g_flag2[b];
        while (*vf == 0) __nanosleep(64);
    }
    __syncthreads();
    __threadfence();                             // acquire
    float S2 = g_S2[b];
    int c1 = g_cnt1[b];                          // final: all E1 done before flag2

    // ---- E2 from registers: s >= S2 and bin < own T1 (exact complement of E1) ----
    if (tid == 0) s_n = 0;
    __syncthreads();
#pragma unroll
    for (int j = 0; j < 4; j++) {
        if (ss[j] >= S2 && (ford(ss[j]) >> 20) < T1) {
            int p = atomicAdd(&s_n, 1);
            sbuf[p] = tile0 + tid * 4 + j;
        }
    }
    __syncthreads();
    if (tid == 0) s_pos = s_n ? (c1 + atomicAdd(&g_cnt2[b], s_n)) : 0;
    __syncthreads();
    n = s_n; pos = s_pos;
    for (int j = warp; j < n; j += 8) {
        u64 key = evalCand(cls, obj, qual, b, sbuf[j], lane);
        if (lane == 0) g_keys[(size_t)b * NPB + pos + j] = key;
    }
    if (lane == 0) __threadfence();
    __syncthreads();

    // ---- ticket3: last block of batch finalizes (no spin, no extra blocks) ----
    if (tid == 0) s_last = (atomicAdd(&g_tick3[b], 1) == BPB - 1) ? 1 : 0;
    __syncthreads();
    if (!s_last) return;

    // ======== finalize batch b: exact top-100 over all M evaluated keys ========
    int M = c1 + g_cnt2[b];
    const u64* keys = g_keys + (size_t)b * NPB;

    for (int j = tid; j < NBIN; j += 256) shh[j] = 0;
    __syncthreads();
    for (int j = tid; j < M; j += 256)
        atomicAdd(&shh[(u32)(keys[j] >> 35)], 1u);
    __syncthreads();
    pickTop(shh, 16, wsum, TOPKK, &s_d, &s_L, &s_C);
    u64 P = (u64)(u32)s_d;
    int s = 35, L = s_L, C = s_C;
    __syncthreads();

    // 10-bit refinement (25, 15, 5); L < 100 invariant; at s=5 bucket <= 32 -> C <= 131.
    u32* subh = reinterpret_cast<u32*>(sbuf);
    while (C > CANDCAP && s > 5) {
        int s2 = s - 10;
        for (int j = tid; j < 1024; j += 256) subh[j] = 0;
        __syncthreads();
        for (int j = tid; j < M; j += 256) {
            u64 k = keys[j];
            if ((k >> s) == P) atomicAdd(&subh[(u32)(k >> s2) & 1023], 1u);
        }
        __syncthreads();
        pickTop(subh, 4, wsum, TOPKK - L, &s_d, &s_L, &s_C);
        int Lsub = s_L, Csub = s_C;
        __syncthreads();
        P = (P << 10) | (u32)s_d;
        s = s2;
        C = L + Csub;
        L = L + Lsub;
    }

    if (tid == 0) s_cnt = 0;
    __syncthreads();
    for (int j = tid; j < M; j += 256) {
        u64 k = keys[j];
        if ((k >> s) >= P) {
            int p = atomicAdd(&s_cnt, 1);
            if (p < CANDCAP) cand[p] = k;
        }
    }
    __syncthreads();
    int Cn = min(s_cnt, CANDCAP);

    // rank by counting (keys distinct -> exact permutation), decode inline
    for (int i = tid; i < Cn; i += 256) {
        u64 k = cand[i];
        int r = 0;
        for (int j = 0; j < Cn; j++) r += (cand[j] > k);
        if (r < TOPKK) {
            u32 sb = (u32)(k >> 17);
            int idx = NPB - 1 - (int)(k & 0x1FFFFu);
            int a = idx / HW;
            int pix = idx - a * HW;
            int y = pix / WW;
            int x = pix - y * WW;
            int c = (int)g_cls[b * NPB + idx];
            const float* bp = box + (size_t)(b * NA + a) * 4 * HW + pix;
            float tx = bp[0];
            float ty = bp[(size_t)HW];
            float tw = bp[2 * (size_t)HW];
            float th = bp[3 * (size_t)HW];
            float aw = anch[a * 2 + 0];
            float ah = anch[a * 2 + 1];
            float cx = (fsig(tx) + (float)x) / (float)WW;
            float cy = (fsig(ty) + (float)y) / (float)HH;
            // faithful softplus: relu(x) + log1p(exp(-|x|))
            float spw = fmaxf(tw, 0.0f) + log1pf(__expf(-fabsf(tw)));
            float sph = fmaxf(th, 0.0f) + log1pf(__expf(-fabsf(th)));
            float* o = out + ((size_t)b * TOPKK + r) * 6;
            o[0] = __uint_as_float(sb);
            o[1] = (float)c;
            o[2] = cx;
            o[3] = cy;
            o[4] = aw * spw;
            o[5] = ah * sph;
        }
    }

    // reset batch-b scratch for the next replay (device globals start zeroed on load)
    __syncthreads();
    for (int j = tid; j < NBIN; j += 256) g_schist[b * NBIN + j] = 0;
    if (tid == 0) {
        g_cnt1[b] = 0; g_cnt2[b] = 0;
        g_tick2[b] = 0; g_tick3[b] = 0; g_flag2[b] = 0;
    }
}

// ---------------- launch ----------------
extern "C" void kernel_launch(void* const* d_in, const int* in_sizes, int n_in,
                              void* d_out, int out_size) {
    const float* box  = (const float*)d_in[0];
    const float* obj  = (const float*)d_in[1];
    const float* qual = (const float*)d_in[2];
    const float* cls  = (const float*)d_in[3];
    const float* anch = (const float*)d_in[4];
    int seen = 0;
    for (int i = 0; i < n_in; i++) {
        int s = in_sizes[i];
        if (s == BATCH * NA * 4 * HW) box = (const float*)d_in[i];
        else if (s == BATCH * NA * NC * HW) cls = (const float*)d_in[i];
        else if (s == NA * 2) anch = (const float*)d_in[i];
        else if (s == BATCH * NA * HW) {
            if (seen == 0) obj = (const float*)d_in[i];
            else qual = (const float*)d_in[i];
            seen++;
        }
    }
    float* out = (float*)d_out;

    fusedK<<<BATCH * BPB, 256>>>(cls, obj, qual, box, anch, out);
}